// round 10
// baseline (speedup 1.0000x reference)
#include <cuda_runtime.h>
#include <cuda_bf16.h>
#include <cstdint>
#include <math.h>

#define NIMG 8
#define CS   128
#define CT   256
#define PIX  4096           // 64*64
#define DTOT (CT*PIX)       // per image

// ---- scratch (__device__ globals; no allocation allowed) ----
__device__ float g_t[(size_t)NIMG*CT*PIX];
__device__ double g_acc[72];

// conv1 output: COMPACT odd-parity pixels only, [img][kc(8)][pix2048][32ch]
__device__ __align__(16) __nv_bfloat16 g_mHi[(size_t)NIMG*8*2048*32];
__device__ __align__(16) __nv_bfloat16 g_mLo[(size_t)NIMG*8*2048*32];
// gen1 output: dense [img][kc(8)][pix4096][32ch]
__device__ __align__(16) __nv_bfloat16 g_g1Hi[(size_t)NIMG*8*4096*32];
__device__ __align__(16) __nv_bfloat16 g_g1Lo[(size_t)NIMG*8*4096*32];

// conv1 weights (row-major hi/lo)
__device__ __align__(16) __nv_bfloat16 g_WaHi[256*128], g_WaLo[256*128];
// conv2/3 weights packed for 512-thread BK=64 stages:
// chunk = tap*4 + kc2 (36 chunks); within 32768 elems: r(0..4095)*8 + j
// r = hilo*2048 + khalf*256 + co
__device__ __align__(16) __nv_bfloat16 g_W1p[36*32768];
__device__ __align__(16) __nv_bfloat16 g_W2p[36*32768];

// =====================================================================
// helpers (sm_80+ baseline PTX)
// =====================================================================
__device__ __forceinline__ uint32_t smem_u32(const void* p) {
    uint32_t a;
    asm("{ .reg .u64 t; cvta.to.shared.u64 t, %1; cvt.u32.u64 %0, t; }" : "=r"(a) : "l"(p));
    return a;
}
__device__ __forceinline__ void ldsm4(uint32_t* r, uint32_t addr) {
    asm volatile("ldmatrix.sync.aligned.m8n8.x4.shared.b16 {%0,%1,%2,%3}, [%4];"
                 : "=r"(r[0]), "=r"(r[1]), "=r"(r[2]), "=r"(r[3]) : "r"(addr));
}
__device__ __forceinline__ void mma16816(float* c, const uint32_t* a, uint32_t b0, uint32_t b1) {
    asm volatile("mma.sync.aligned.m16n8k16.row.col.f32.bf16.bf16.f32 "
                 "{%0,%1,%2,%3}, {%4,%5,%6,%7}, {%8,%9}, {%0,%1,%2,%3};"
                 : "+f"(c[0]), "+f"(c[1]), "+f"(c[2]), "+f"(c[3])
                 : "r"(a[0]), "r"(a[1]), "r"(a[2]), "r"(a[3]), "r"(b0), "r"(b1));
}
__device__ __forceinline__ void cp16(uint32_t dst, const void* src, uint32_t sz) {
    asm volatile("cp.async.cg.shared.global [%0], [%1], 16, %2;"
                 :: "r"(dst), "l"(src), "r"(sz) : "memory");
}
__device__ __forceinline__ void cp_commit() {
    asm volatile("cp.async.commit_group;" ::: "memory");
}
__device__ __forceinline__ void cp_wait1() {
    asm volatile("cp.async.wait_group 1;" ::: "memory");
}
__device__ __forceinline__ void bf16split(float v, __nv_bfloat16& h, __nv_bfloat16& l) {
    h = __float2bfloat16(v);
    l = __float2bfloat16(v - __bfloat162float(h));
}

// =====================================================================
// Weight prep (512-thread BK=64 packing, chunk = tap*4 + kc2)
// =====================================================================
__global__ void wprep_kernel(const float* __restrict__ Wa, const float* __restrict__ W1,
                             const float* __restrict__ W2) {
    int t = blockIdx.x * blockDim.x + threadIdx.x;
    if (t < 256*128) {
        float v = Wa[t];
        __nv_bfloat16 h, l;
        bf16split(v, h, l);
        g_WaHi[t] = h; g_WaLo[t] = l;
    }
    int u = t - 256*128;
    if (u >= 0 && u < 36*32768) {
        int chunk  = u >> 15;
        int within = u & 32767;
        int r = within >> 3, j = within & 7;
        int tap = chunk >> 2;
        int kc2 = chunk & 3;
        int hilo  = r >> 11;
        int khalf = (r >> 8) & 7;
        int co    = r & 255;
        int ci    = kc2 * 64 + khalf * 8 + j;
        int src   = co * 2304 + ci * 9 + tap;
        {
            __nv_bfloat16 h, l;
            bf16split(W1[src], h, l);
            g_W1p[u] = hilo ? l : h;
        }
        {
            __nv_bfloat16 h, l;
            bf16split(W2[src], h, l);
            g_W2p[u] = hilo ? l : h;
        }
    }
}

__global__ void init_kernel() {
    if (threadIdx.x < 72) g_acc[threadIdx.x] = 0.0;
}

// =====================================================================
// conv1 (1x1, K=128): odd-parity pixels only (verified).
// =====================================================================
__global__ __launch_bounds__(256, 2)
void conv1_mma(const __nv_bfloat16* __restrict__ Whi, const __nv_bfloat16* __restrict__ Wlo,
               const float* __restrict__ bias, const float* __restrict__ in,
               __nv_bfloat16* __restrict__ outHi, __nv_bfloat16* __restrict__ outLo) {
    extern __shared__ char sm[];
    const int tid  = threadIdx.x;
    const int lane = tid & 31, wid = tid >> 5;
    const int m0   = blockIdx.y * 128;
    const int bx   = blockIdx.x;
    const int img  = bx >> 4;
    const int pix0 = (bx & 15) * 128;
    const float* inImg = in + (size_t)img * CS * PIX;

    constexpr int NCH = CS / 32;  // 4

    const int a_row = tid >> 1;
    const int a_k0  = (tid & 1) * 16;
    const int b_n   = tid & 127;
    const int b_sg  = tid >> 7;
    const int cpx  = pix0 + b_n;
    const int ch_h = cpx >> 5;
    const int ch_w = 2 * (cpx & 31) + ((ch_h + 1) & 1);
    const int bsrc = ch_h * 64 + ch_w;

    uint4 rAh[2], rAl[2];
    float rB[16];

    auto ldg_chunk = [&](int it) {
        const int c0 = it * 32;
        size_t aoff = (size_t)(m0 + a_row) * CS + c0 + a_k0;
        rAh[0] = *(const uint4*)(Whi + aoff);
        rAh[1] = *(const uint4*)(Whi + aoff + 8);
        rAl[0] = *(const uint4*)(Wlo + aoff);
        rAl[1] = *(const uint4*)(Wlo + aoff + 8);
        const float* p = inImg + (size_t)(c0 + b_sg * 16) * PIX + bsrc;
#pragma unroll
        for (int q = 0; q < 16; q++)
            rB[q] = __ldg(p + (size_t)q * PIX);
    };

    auto sts_chunk = [&](int s) {
        char* Ahi = sm + s * 32768;
        char* Alo = Ahi + 8192;
        char* Bhi = Ahi + 16384;
        char* Blo = Ahi + 24576;
        const int kh0 = a_k0 >> 3;
        *(uint4*)(Ahi + (kh0    ) * 2048 + a_row * 16) = rAh[0];
        *(uint4*)(Ahi + (kh0 + 1) * 2048 + a_row * 16) = rAh[1];
        *(uint4*)(Alo + (kh0    ) * 2048 + a_row * 16) = rAl[0];
        *(uint4*)(Alo + (kh0 + 1) * 2048 + a_row * 16) = rAl[1];
#pragma unroll
        for (int g = 0; g < 2; g++) {
            uint32_t hp[4], lp[4];
#pragma unroll
            for (int jp = 0; jp < 4; jp++) {
                float x0 = rB[g * 8 + 2 * jp], x1 = rB[g * 8 + 2 * jp + 1];
                __nv_bfloat16 hb0, lb0, hb1, lb1;
                bf16split(x0, hb0, lb0);
                bf16split(x1, hb1, lb1);
                hp[jp] = (uint32_t)__bfloat16_as_ushort(hb0)
                       | ((uint32_t)__bfloat16_as_ushort(hb1) << 16);
                lp[jp] = (uint32_t)__bfloat16_as_ushort(lb0)
                       | ((uint32_t)__bfloat16_as_ushort(lb1) << 16);
            }
            const int kh = b_sg * 2 + g;
            *(uint4*)(Bhi + kh * 2048 + b_n * 16) = make_uint4(hp[0], hp[1], hp[2], hp[3]);
            *(uint4*)(Blo + kh * 2048 + b_n * 16) = make_uint4(lp[0], lp[1], lp[2], lp[3]);
        }
    };

    float acc[4][4][4];
#pragma unroll
    for (int i = 0; i < 4; i++)
#pragma unroll
        for (int j = 0; j < 4; j++)
#pragma unroll
            for (int k = 0; k < 4; k++) acc[i][j][k] = 0.f;

    const int warp_m = wid & 1;
    const int warp_n = wid >> 1;
    const uint32_t smem0 = smem_u32(sm);
    const int lrow = (lane & 7) + ((lane >> 3) & 1) * 8;
    const int lkh  = (lane >> 4);

    ldg_chunk(0);
    sts_chunk(0);
    __syncthreads();

    for (int it = 0; it < NCH; ++it) {
        if (it + 1 < NCH) ldg_chunk(it + 1);
        const uint32_t S = smem0 + (it & 1) * 32768;
#pragma unroll
        for (int k16 = 0; k16 < 2; ++k16) {
            const uint32_t kbase = S + (k16 * 2 + lkh) * 2048;
            uint32_t bh[2][4], bl[2][4];
#pragma unroll
            for (int ng = 0; ng < 2; ++ng) {
                const uint32_t bd = kbase + 16384 + (warp_n * 32 + ng * 16 + lrow) * 16;
                ldsm4(bh[ng], bd);
                ldsm4(bl[ng], bd + 8192);
            }
#pragma unroll
            for (int mt = 0; mt < 4; ++mt) {
                uint32_t ah[4], al[4];
                const uint32_t ad = kbase + (warp_m * 64 + mt * 16 + lrow) * 16;
                ldsm4(ah, ad);
                ldsm4(al, ad + 8192);
#pragma unroll
                for (int nt = 0; nt < 4; ++nt)
                    mma16816(acc[mt][nt], ah, bh[nt >> 1][nt & 1], bh[nt >> 1][2 + (nt & 1)]);
#pragma unroll
                for (int nt = 0; nt < 4; ++nt)
                    mma16816(acc[mt][nt], ah, bl[nt >> 1][nt & 1], bl[nt >> 1][2 + (nt & 1)]);
#pragma unroll
                for (int nt = 0; nt < 4; ++nt)
                    mma16816(acc[mt][nt], al, bh[nt >> 1][nt & 1], bh[nt >> 1][2 + (nt & 1)]);
            }
        }
        if (it + 1 < NCH) sts_chunk((it + 1) & 1);
        __syncthreads();
    }

    const int l4 = lane >> 2, l2 = lane & 3;
    const size_t imgbase = (size_t)img * 8 * 2048 * 32;
#pragma unroll
    for (int mt = 0; mt < 4; ++mt) {
        const int co0 = m0 + warp_m * 64 + mt * 16 + l4;
        const float bi0 = bias[co0], bi1 = bias[co0 + 8];
#pragma unroll
        for (int nt = 0; nt < 4; ++nt) {
            const int p = pix0 + warp_n * 32 + nt * 8 + l2 * 2;
            float v0 = acc[mt][nt][0] + bi0;
            float v1 = acc[mt][nt][1] + bi0;
            float v2 = acc[mt][nt][2] + bi1;
            float v3 = acc[mt][nt][3] + bi1;
            const size_t o00 = imgbase + ((size_t)(co0 >> 5) * 2048 + p) * 32 + (co0 & 31);
            const size_t o10 = imgbase + ((size_t)((co0 + 8) >> 5) * 2048 + p) * 32 + ((co0 + 8) & 31);
            __nv_bfloat16 h, l;
            bf16split(v0, h, l); outHi[o00]      = h; outLo[o00]      = l;
            bf16split(v1, h, l); outHi[o00 + 32] = h; outLo[o00 + 32] = l;
            bf16split(v2, h, l); outHi[o10]      = h; outLo[o10]      = l;
            bf16split(v3, h, l); outHi[o10 + 32] = h; outLo[o10 + 32] = l;
        }
    }
}

// =====================================================================
// Shared 512-thread BK=64 conv core
// Stage (96KB): A 64KB at +0, B 32KB at +65536.
// Consumer: wide pass-major (dependent-MMA spacing >= 12).
// =====================================================================
#define STG 98304

// Consumer body for one k16 slice. Dependent-accumulator reuse spacing:
// pass1->pass2 = 16 MMAs, pass2->pass3 = 16, pass3->next-k16 pass1 >= 12.
#define K16_BODY(kbA, kbB)                                                          \
    {                                                                               \
        uint32_t bh[2][4], bl[2][4], ah[4][4];                                      \
        _Pragma("unroll")                                                           \
        for (int ng = 0; ng < 2; ++ng) {                                            \
            const uint32_t bd = (kbB) + (warp_n * 32 + ng * 16 + lrow) * 16;        \
            ldsm4(bh[ng], bd);                                                      \
            ldsm4(bl[ng], bd + 16384);                                              \
        }                                                                           \
        _Pragma("unroll")                                                           \
        for (int mt = 0; mt < 4; ++mt)                                              \
            ldsm4(ah[mt], (kbA) + (warp_m * 64 + mt * 16 + lrow) * 16);             \
        _Pragma("unroll")                                                           \
        for (int mt = 0; mt < 4; ++mt)                                              \
            _Pragma("unroll")                                                       \
            for (int nt = 0; nt < 4; ++nt)                                          \
                mma16816(acc[mt][nt], ah[mt],                                       \
                         bh[nt >> 1][nt & 1], bh[nt >> 1][2 + (nt & 1)]);           \
        _Pragma("unroll")                                                           \
        for (int mt = 0; mt < 4; ++mt)                                              \
            _Pragma("unroll")                                                       \
            for (int nt = 0; nt < 4; ++nt)                                          \
                mma16816(acc[mt][nt], ah[mt],                                       \
                         bl[nt >> 1][nt & 1], bl[nt >> 1][2 + (nt & 1)]);           \
        _Pragma("unroll")                                                           \
        for (int mt = 0; mt < 4; ++mt) {                                            \
            uint32_t al[4];                                                         \
            ldsm4(al, (kbA) + 32768 + (warp_m * 64 + mt * 16 + lrow) * 16);         \
            _Pragma("unroll")                                                       \
            for (int nt = 0; nt < 4; ++nt)                                          \
                mma16816(acc[mt][nt], al,                                           \
                         bh[nt >> 1][nt & 1], bh[nt >> 1][2 + (nt & 1)]);           \
        }                                                                           \
    }

// conv2 (gen1, polyphase): grid 256 = img*32 + P*16 + htile. 512 thr.
__global__ __launch_bounds__(512, 1)
void conv2_poly(const __nv_bfloat16* __restrict__ Wp,
                const float* __restrict__ bias,
                const __nv_bfloat16* __restrict__ actHi,
                const __nv_bfloat16* __restrict__ actLo,
                __nv_bfloat16* __restrict__ outHi,
                __nv_bfloat16* __restrict__ outLo) {
    extern __shared__ char sm[];
    const int tid  = threadIdx.x;
    const int lane = tid & 31, wid = tid >> 5;
    const int bx   = blockIdx.x;
    const int img  = bx >> 5;
    const int rem  = bx & 31;
    const int P    = rem >> 4;
    const int h0   = (rem & 15) * 4;

    const int NT  = 4 + P;
    const int NCH = NT * 4;
    const uint32_t smem0 = smem_u32(sm);
    const uint32_t dstA0 = smem0 + tid * 16;
    const uint32_t dstB0 = smem0 + 65536 + tid * 16;

    const __nv_bfloat16* aPtr = Wp + tid * 8;
    uint32_t bOff[2];
    uint32_t bOk = 0;

    auto setup_tap = [&](int tap_t) {
        const int tapid = P ? (2 * tap_t) : (2 * tap_t + 1);
        const int dh = tapid / 3 - 1, dw = tapid % 3 - 1;
        aPtr = Wp + (size_t)tapid * 4 * 32768 + tid * 8;
        bOk = 0;
#pragma unroll
        for (int r = 0; r < 2; ++r) {
            const int br = tid + 512 * r;
            const int khalf = (br >> 7) & 7;
            const int px    = br & 127;
            const int row = h0 + (px >> 5);
            const int ow  = 2 * (px & 31) + ((P + row) & 1);
            const int h = row + dh, w = ow + dw;
            const bool ok = ((unsigned)h < 64u) & ((unsigned)w < 64u);
            const int ci = ok ? ((w - ((h + 1) & 1)) >> 1) : 0;
            const int hpix = ok ? (h * 32 + ci) : 0;
            bOff[r] = ((uint32_t)(img * 8 + (khalf >> 2)) * 2048 + hpix) * 32 + (khalf & 3) * 8;
            bOk |= (ok ? 1u : 0u) << r;
        }
    };

    auto issue = [&](int it) {
        const uint32_t sb = (uint32_t)(it & 1) * STG;
        const int kc2 = it & 3;
        if (kc2 == 0) setup_tap(it >> 2);
        const __nv_bfloat16* a = aPtr + kc2 * 32768;
#pragma unroll
        for (int i = 0; i < 8; i++)
            cp16(dstA0 + sb + 8192u * i, a + 4096 * i, 16u);
        const uint32_t kadd = (uint32_t)kc2 * 131072u;
        const uint32_t s0 = (bOk & 1u) ? 16u : 0u;
        const uint32_t s1 = (bOk & 2u) ? 16u : 0u;
        cp16(dstB0 + sb,         actHi + bOff[0] + kadd, s0);
        cp16(dstB0 + sb + 8192,  actHi + bOff[1] + kadd, s1);
        cp16(dstB0 + sb + 16384, actLo + bOff[0] + kadd, s0);
        cp16(dstB0 + sb + 24576, actLo + bOff[1] + kadd, s1);
    };

    float acc[4][4][4];
#pragma unroll
    for (int i = 0; i < 4; i++)
#pragma unroll
        for (int j = 0; j < 4; j++)
#pragma unroll
            for (int k = 0; k < 4; k++) acc[i][j][k] = 0.f;

    const int warp_m = wid >> 2;
    const int warp_n = wid & 3;
    const int lrow = (lane & 7) + ((lane >> 3) & 1) * 8;
    const int lkh  = (lane >> 4);

    issue(0); cp_commit();

    for (int it = 0; it < NCH; ++it) {
        if (it + 1 < NCH) issue(it + 1);
        cp_commit();
        cp_wait1();
        __syncthreads();

        const uint32_t S = smem0 + (it & 1) * STG;
#pragma unroll
        for (int k16 = 0; k16 < 4; ++k16) {
            const int khl = k16 * 2 + lkh;
            const uint32_t kbA = S + khl * 4096;
            const uint32_t kbB = S + 65536 + khl * 2048;
            K16_BODY(kbA, kbB)
        }
        __syncthreads();
    }

    // epilogue: bias + relu, scatter to dense hi/lo planes
    const int l4 = lane >> 2, l2 = lane & 3;
    const int row = h0 + warp_n;
    const int wpar = (P + row) & 1;
    const size_t imgbase = (size_t)img * 8 * 4096 * 32;
#pragma unroll
    for (int mt = 0; mt < 4; ++mt) {
        const int co0 = warp_m * 64 + mt * 16 + l4;
        const float bi0 = bias[co0], bi1 = bias[co0 + 8];
        const size_t cb0 = imgbase + (size_t)(co0 >> 5) * 4096 * 32 + (co0 & 31);
        const size_t cb1 = imgbase + (size_t)((co0 + 8) >> 5) * 4096 * 32 + ((co0 + 8) & 31);
#pragma unroll
        for (int nt = 0; nt < 4; ++nt) {
            const int j0 = nt * 8 + l2 * 2;
            const int pix0e = row * 64 + 2 * j0 + wpar;
            const int pix1e = pix0e + 2;
            float v0 = fmaxf(acc[mt][nt][0] + bi0, 0.f);
            float v1 = fmaxf(acc[mt][nt][1] + bi0, 0.f);
            float v2 = fmaxf(acc[mt][nt][2] + bi1, 0.f);
            float v3 = fmaxf(acc[mt][nt][3] + bi1, 0.f);
            __nv_bfloat16 h, l;
            bf16split(v0, h, l); outHi[cb0 + (size_t)pix0e * 32] = h; outLo[cb0 + (size_t)pix0e * 32] = l;
            bf16split(v1, h, l); outHi[cb0 + (size_t)pix1e * 32] = h; outLo[cb0 + (size_t)pix1e * 32] = l;
            bf16split(v2, h, l); outHi[cb1 + (size_t)pix0e * 32] = h; outLo[cb1 + (size_t)pix0e * 32] = l;
            bf16split(v3, h, l); outHi[cb1 + (size_t)pix1e * 32] = h; outLo[cb1 + (size_t)pix1e * 32] = l;
        }
    }
}

// conv3 (dense 3x3): grid 256 = img*32 + pixtile. 512 thr, fp32 out.
__global__ __launch_bounds__(512, 1)
void conv3_cp(const __nv_bfloat16* __restrict__ Wp,
              const float* __restrict__ bias,
              const __nv_bfloat16* __restrict__ actHi,
              const __nv_bfloat16* __restrict__ actLo,
              float* __restrict__ outF32) {
    extern __shared__ char sm[];
    const int tid  = threadIdx.x;
    const int lane = tid & 31, wid = tid >> 5;
    const int bx   = blockIdx.x;
    const int img  = bx >> 5;
    const int pix0 = (bx & 31) * 128;
    const int h0   = pix0 >> 6;

    constexpr int NCH = 36;
    const uint32_t smem0 = smem_u32(sm);
    const uint32_t dstA0 = smem0 + tid * 16;
    const uint32_t dstB0 = smem0 + 65536 + tid * 16;

    const __nv_bfloat16* aPtr = Wp + tid * 8;
    uint32_t bOff[2];
    uint32_t bOk = 0;

    auto setup_tap = [&](int tap) {
        const int dh = tap / 3 - 1, dw = tap % 3 - 1;
        aPtr = Wp + (size_t)tap * 4 * 32768 + tid * 8;
        bOk = 0;
#pragma unroll
        for (int r = 0; r < 2; ++r) {
            const int br = tid + 512 * r;
            const int khalf = (br >> 7) & 7;
            const int px    = br & 127;
            const int h = h0 + (px >> 6) + dh, w = (px & 63) + dw;
            const bool ok = ((unsigned)h < 64u) & ((unsigned)w < 64u);
            const int hpix = ok ? (h * 64 + w) : 0;
            bOff[r] = ((uint32_t)(img * 8 + (khalf >> 2)) * 4096 + hpix) * 32 + (khalf & 3) * 8;
            bOk |= (ok ? 1u : 0u) << r;
        }
    };

    auto issue = [&](int it) {
        const uint32_t sb = (uint32_t)(it & 1) * STG;
        const int kc2 = it & 3;
        if (kc2 == 0) setup_tap(it >> 2);
        const __nv_bfloat16* a = aPtr + kc2 * 32768;
#pragma unroll
        for (int i = 0; i < 8; i++)
            cp16(dstA0 + sb + 8192u * i, a + 4096 * i, 16u);
        const uint32_t kadd = (uint32_t)kc2 * 262144u;
        const uint32_t s0 = (bOk & 1u) ? 16u : 0u;
        const uint32_t s1 = (bOk & 2u) ? 16u : 0u;
        cp16(dstB0 + sb,         actHi + bOff[0] + kadd, s0);
        cp16(dstB0 + sb + 8192,  actHi + bOff[1] + kadd, s1);
        cp16(dstB0 + sb + 16384, actLo + bOff[0] + kadd, s0);
        cp16(dstB0 + sb + 24576, actLo + bOff[1] + kadd, s1);
    };

    float acc[4][4][4];
#pragma unroll
    for (int i = 0; i < 4; i++)
#pragma unroll
        for (int j = 0; j < 4; j++)
#pragma unroll
            for (int k = 0; k < 4; k++) acc[i][j][k] = 0.f;

    const int warp_m = wid >> 2;
    const int warp_n = wid & 3;
    const int lrow = (lane & 7) + ((lane >> 3) & 1) * 8;
    const int lkh  = (lane >> 4);

    issue(0); cp_commit();

    for (int it = 0; it < NCH; ++it) {
        if (it + 1 < NCH) issue(it + 1);
        cp_commit();
        cp_wait1();
        __syncthreads();

        const uint32_t S = smem0 + (it & 1) * STG;
#pragma unroll
        for (int k16 = 0; k16 < 4; ++k16) {
            const int khl = k16 * 2 + lkh;
            const uint32_t kbA = S + khl * 4096;
            const uint32_t kbB = S + 65536 + khl * 2048;
            K16_BODY(kbA, kbB)
        }
        __syncthreads();
    }

    const int l4 = lane >> 2, l2 = lane & 3;
    float* outImg = outF32 + (size_t)img * CT * PIX;
#pragma unroll
    for (int mt = 0; mt < 4; ++mt) {
        const int co0 = warp_m * 64 + mt * 16 + l4;
        const float bi0 = bias[co0], bi1 = bias[co0 + 8];
#pragma unroll
        for (int nt = 0; nt < 4; ++nt) {
            const int p = pix0 + warp_n * 32 + nt * 8 + l2 * 2;
            float v0 = acc[mt][nt][0] + bi0;
            float v1 = acc[mt][nt][1] + bi0;
            float v2 = acc[mt][nt][2] + bi1;
            float v3 = acc[mt][nt][3] + bi1;
            *(float2*)(outImg + (size_t)co0 * PIX + p)       = make_float2(v0, v1);
            *(float2*)(outImg + (size_t)(co0 + 8) * PIX + p) = make_float2(v2, v3);
        }
    }
}

// =====================================================================
// pairwise dots + target norms (unchanged, verified)
// =====================================================================
__global__ __launch_bounds__(256)
void dot_kernel(const float* __restrict__ p, const float* __restrict__ t) {
    const int tid = threadIdx.x;
    const int d0  = blockIdx.x * 2048 + tid;

    float dacc[8][8];
    float tn[8];
#pragma unroll
    for (int i = 0; i < 8; i++) {
        tn[i] = 0.f;
#pragma unroll
        for (int j = 0; j < 8; j++) dacc[i][j] = 0.f;
    }
#pragma unroll 2
    for (int it = 0; it < 8; it++) {
        int d = d0 + it * 256;
        float pv[8], tv[8];
#pragma unroll
        for (int i = 0; i < 8; i++) {
            pv[i] = __ldg(p + (size_t)i * DTOT + d);
            tv[i] = __ldg(t + (size_t)i * DTOT + d);
        }
#pragma unroll
        for (int j = 0; j < 8; j++) tn[j] = fmaf(tv[j], tv[j], tn[j]);
#pragma unroll
        for (int i = 0; i < 8; i++)
#pragma unroll
            for (int j = 0; j < 8; j++)
                dacc[i][j] = fmaf(pv[i], tv[j], dacc[i][j]);
    }
    __shared__ float red[8][72];
    const int lane = tid & 31, warp = tid >> 5;
#pragma unroll
    for (int i = 0; i < 8; i++)
#pragma unroll
        for (int j = 0; j < 8; j++) {
            float v = dacc[i][j];
#pragma unroll
            for (int s = 16; s; s >>= 1) v += __shfl_xor_sync(0xFFFFFFFFu, v, s);
            if (lane == 0) red[warp][i*8+j] = v;
        }
#pragma unroll
    for (int j = 0; j < 8; j++) {
        float v = tn[j];
#pragma unroll
        for (int s = 16; s; s >>= 1) v += __shfl_xor_sync(0xFFFFFFFFu, v, s);
        if (lane == 0) red[warp][64+j] = v;
    }
    __syncthreads();
    if (tid < 72) {
        double s = 0.0;
#pragma unroll
        for (int w = 0; w < 8; w++) s += (double)red[w][tid];
        atomicAdd(&g_acc[tid], s);
    }
}

__global__ void finalize_kernel(float* __restrict__ out) {
    if (threadIdx.x != 0 || blockIdx.x != 0) return;
    double L[8][8];
    for (int i = 0; i < 8; i++)
        for (int j = 0; j < 8; j++)
            L[i][j] = (g_acc[i*8+j] - 0.5 * g_acc[64+j]) / 64.0;
    double ce = 0.0;
    for (int i = 0; i < 8; i++) {
        double m = L[i][0];
        for (int j = 1; j < 8; j++) m = L[i][j] > m ? L[i][j] : m;
        double s = 0.0;
        for (int j = 0; j < 8; j++) s += exp(L[i][j] - m);
        ce += (m + log(s)) - L[i][i];
    }
    ce /= 8.0;
    double loss = ce * (2.0 * 64.0 / 8.0) * 2e-05;
    out[0] = (float)loss;
}

// =====================================================================
extern "C" void kernel_launch(void* const* d_in, const int* in_sizes, int n_in,
                              void* d_out, int out_size) {
    const float* S  = (const float*)d_in[0];
    const float* T  = (const float*)d_in[1];
    const float* Wa = (const float*)d_in[2];
    const float* ba = (const float*)d_in[3];
    const float* W1 = (const float*)d_in[4];
    const float* b1 = (const float*)d_in[5];
    const float* W2 = (const float*)d_in[6];
    const float* b2 = (const float*)d_in[7];
    float* out = (float*)d_out;

    float* tbuf;
    cudaGetSymbolAddress((void**)&tbuf, g_t);
    __nv_bfloat16 *waH, *waL, *w1p, *w2p, *mHi, *mLo, *g1Hi, *g1Lo;
    cudaGetSymbolAddress((void**)&waH, g_WaHi);
    cudaGetSymbolAddress((void**)&waL, g_WaLo);
    cudaGetSymbolAddress((void**)&w1p, g_W1p);
    cudaGetSymbolAddress((void**)&w2p, g_W2p);
    cudaGetSymbolAddress((void**)&mHi, g_mHi);
    cudaGetSymbolAddress((void**)&mLo, g_mLo);
    cudaGetSymbolAddress((void**)&g1Hi, g_g1Hi);
    cudaGetSymbolAddress((void**)&g1Lo, g_g1Lo);

    cudaFuncSetAttribute(conv1_mma,  cudaFuncAttributeMaxDynamicSharedMemorySize, 65536);
    cudaFuncSetAttribute(conv2_poly, cudaFuncAttributeMaxDynamicSharedMemorySize, 2 * STG);
    cudaFuncSetAttribute(conv3_cp,   cudaFuncAttributeMaxDynamicSharedMemorySize, 2 * STG);

    init_kernel<<<1, 128>>>();
    {
        int total = 256*128 + 36*32768;
        wprep_kernel<<<(total + 255) / 256, 256>>>(Wa, W1, W2);
    }
    conv1_mma <<<dim3(128, 2), 256, 65536>>>(waH, waL, ba, S, mHi, mLo);
    conv2_poly<<<256, 512, 2 * STG>>>(w1p, b1, mHi, mLo, g1Hi, g1Lo);
    conv3_cp  <<<256, 512, 2 * STG>>>(w2p, b2, g1Hi, g1Lo, tbuf);

    dot_kernel<<<DTOT / 2048, 256>>>(T, tbuf);
    finalize_kernel<<<1, 1>>>(out);
}